// round 13
// baseline (speedup 1.0000x reference)
#include <cuda_runtime.h>

// Problem constants
#define NBT   96      // B*T
#define NSEQ  512     // N
#define DMODEL 64
#define KH    8
#define HD    8
#define TOKENS (NBT * NSEQ)   // 49152

typedef unsigned long long u64;
typedef unsigned int u32;

// Scratch: q,k,v row-major [h][bt][n][d]; att [tok][64]
__device__ float g_q[KH * NBT * NSEQ * HD];
__device__ float g_k[KH * NBT * NSEQ * HD];
__device__ float g_v[KH * NBT * NSEQ * HD];
__device__ float g_att[TOKENS * DMODEL];

// ---------------- helpers ----------------
__device__ __forceinline__ float ex2(float x) {
    float y; asm("ex2.approx.f32 %0, %1;" : "=f"(y) : "f"(x)); return y;
}

// pack {lo16 = bf16(x0), hi16 = bf16(x1)}
__device__ __forceinline__ u32 cvt_bf2(float x1, float x0) {
    u32 r; asm("cvt.rn.bf16x2.f32 %0, %1, %2;" : "=r"(r) : "f"(x1), "f"(x0)); return r;
}
__device__ __forceinline__ float bflo(u32 p) { return __uint_as_float(p << 16); }
__device__ __forceinline__ float bfhi(u32 p) { return __uint_as_float(p & 0xffff0000u); }
__device__ __forceinline__ void split2(float x0, float x1, u32& hp, u32& lp) {
    hp = cvt_bf2(x1, x0);
    lp = cvt_bf2(x1 - bfhi(hp), x0 - bflo(hp));
}

// m16n8k8 / m16n8k16 bf16 MMA, f32 accumulate, row.col
__device__ __forceinline__ void mma8(float (&d)[4], u32 a0, u32 a1, u32 b) {
    asm("mma.sync.aligned.m16n8k8.row.col.f32.bf16.bf16.f32 "
        "{%0,%1,%2,%3},{%4,%5},{%6},{%0,%1,%2,%3};"
        : "+f"(d[0]), "+f"(d[1]), "+f"(d[2]), "+f"(d[3])
        : "r"(a0), "r"(a1), "r"(b));
}
__device__ __forceinline__ void mma16(float (&d)[4], u32 a0, u32 a1, u32 a2, u32 a3,
                                      u32 b0, u32 b1) {
    asm("mma.sync.aligned.m16n8k16.row.col.f32.bf16.bf16.f32 "
        "{%0,%1,%2,%3},{%4,%5,%6,%7},{%8,%9},{%0,%1,%2,%3};"
        : "+f"(d[0]), "+f"(d[1]), "+f"(d[2]), "+f"(d[3])
        : "r"(a0), "r"(a1), "r"(a2), "r"(a3), "r"(b0), "r"(b1));
}

#define WPAD 72   // row stride for weight smem planes — proven conflict-free

// ---------------------------------------------------------------------------
// Kernel 1: fused QKV projection on tensor cores (R10 proven version).
// ---------------------------------------------------------------------------
__global__ __launch_bounds__(256) void qkv_kernel(
    const float* __restrict__ X, const float* __restrict__ STE,
    const float* __restrict__ W7, const float* __restrict__ b7,
    const float* __restrict__ W8, const float* __restrict__ b8,
    const float* __restrict__ W9, const float* __restrict__ b9)
{
    __shared__ __align__(16) u32 swh[64 * WPAD];
    __shared__ __align__(16) u32 swl[64 * WPAD];

    const int mat = blockIdx.y;
    const float* W  = (mat == 0) ? W7 : (mat == 1) ? W8 : W9;
    const float* bv = (mat == 0) ? b7 : (mat == 1) ? b8 : b9;
    float* gout     = (mat == 0) ? g_q : (mat == 1) ? g_k : g_v;

    const int tid  = threadIdx.x;
    const int lane = tid & 31;
    const int warp = tid >> 5;
    const int row0 = blockIdx.x * 128;
    const int bt   = row0 >> 9;
    const int n0b  = row0 & 511;
    const int gr   = lane >> 2;
    const int kc   = lane & 3;

    #pragma unroll
    for (int e = 0; e < 16; e++) {
        int idx = e * 256 + tid;
        int k2 = idx >> 6, n = idx & 63;
        float w0 = W[(2 * k2) * 64 + n];
        float w1 = W[(2 * k2 + 1) * 64 + n];
        u32 hp, lp;
        split2(w0, w1, hp, lp);
        swh[k2 * WPAD + n] = hp;
        swl[k2 * WPAD + n] = lp;
    }
    __syncthreads();

    float c[8][4];
    #pragma unroll
    for (int nt = 0; nt < 8; nt++)
        #pragma unroll
        for (int e = 0; e < 4; e++) c[nt][e] = 0.0f;

    const int r0 = row0 + warp * 16 + gr;

    #pragma unroll 1
    for (int ks = 0; ks < 16; ks++) {
        const float* src = (ks < 8) ? X : STE;
        const int kk = (ks & 7) * 8 + kc * 2;
        float2 f0 = *(const float2*)(src + r0 * 64 + kk);
        float2 f1 = *(const float2*)(src + (r0 + 8) * 64 + kk);
        u32 ah0, al0, ah1, al1;
        split2(f0.x, f0.y, ah0, al0);
        split2(f1.x, f1.y, ah1, al1);

        const u32* bh = &swh[(ks * 4 + kc) * WPAD + gr];
        const u32* bl = &swl[(ks * 4 + kc) * WPAD + gr];
        #pragma unroll
        for (int nt = 0; nt < 8; nt++) {
            u32 wbh = bh[nt * 8];
            u32 wbl = bl[nt * 8];
            mma16(c[nt], ah0, ah1, al0, al1, wbh, wbh);
            mma8(c[nt], ah0, ah1, wbl);
        }
    }

    const int n_lo = n0b + warp * 16 + gr;
    #pragma unroll
    for (int nt = 0; nt < 8; nt++) {
        const int d0 = kc * 2;
        float bx = bv[nt * 8 + d0], by = bv[nt * 8 + d0 + 1];
        float2 oA = make_float2(fmaxf(c[nt][0] + bx, 0.0f), fmaxf(c[nt][1] + by, 0.0f));
        float2 oB = make_float2(fmaxf(c[nt][2] + bx, 0.0f), fmaxf(c[nt][3] + by, 0.0f));
        float* dst = &gout[(((nt * NBT) + bt) * NSEQ + n_lo) * HD + d0];
        *(float2*)dst            = oA;
        *(float2*)(dst + 8 * HD) = oB;
    }
}

// ---------------------------------------------------------------------------
// Kernel 2: attention per (bt, head). 16 warps x 32 rows (R12) PLUS one-chunk
// score lookahead: ex2(cur) issues before the independent scores(next) MMAs,
// so MUFU and tensor pipes overlap within each warp. PV 2-term, consistent
// denominator. grid (96, 8), 512 threads.
// ---------------------------------------------------------------------------
__global__ __launch_bounds__(512) void attn_kernel()
{
    __shared__ __align__(16) u32 skh[NSEQ * 4];       // K hi pairs [j][c]
    __shared__ __align__(16) u32 skl[NSEQ * 4];
    __shared__ __align__(16) u32 svh[(NSEQ / 2) * 8]; // V hi pairs [j2][d]
    __shared__ __align__(16) u32 svl[(NSEQ / 2) * 8];

    const int bt   = blockIdx.x;
    const int h    = blockIdx.y;
    const int tid  = threadIdx.x;
    const int lane = tid & 31;
    const int warp = tid >> 5;
    const int base = (h * NBT + bt) * NSEQ * HD;

    // stage K -> bf16 hi/lo pairs over d (one row per thread)
    {
        int r = tid;
        const float4* kp = (const float4*)(g_k + base + r * 8);
        float4 f0 = kp[0], f1 = kp[1];
        u32 h0, l0, h1, l1, h2, l2, h3, l3;
        split2(f0.x, f0.y, h0, l0);
        split2(f0.z, f0.w, h1, l1);
        split2(f1.x, f1.y, h2, l2);
        split2(f1.z, f1.w, h3, l3);
        *(uint4*)&skh[r * 4] = make_uint4(h0, h1, h2, h3);
        *(uint4*)&skl[r * 4] = make_uint4(l0, l1, l2, l3);
    }

    // stage V -> pairs over j at fixed d (one (j2, d-group) per thread)
    {
        int j2 = tid & 255, dg = tid >> 8;
        const float* vb = g_v + base + (2 * j2) * 8 + dg * 4;
        float4 f0 = *(const float4*)vb;
        float4 f1 = *(const float4*)(vb + 8);
        u32 hp, lp;
        split2(f0.x, f1.x, hp, lp); svh[j2 * 8 + dg * 4 + 0] = hp; svl[j2 * 8 + dg * 4 + 0] = lp;
        split2(f0.y, f1.y, hp, lp); svh[j2 * 8 + dg * 4 + 1] = hp; svl[j2 * 8 + dg * 4 + 1] = lp;
        split2(f0.z, f1.z, hp, lp); svh[j2 * 8 + dg * 4 + 2] = hp; svl[j2 * 8 + dg * 4 + 2] = lp;
        split2(f0.w, f1.w, hp, lp); svh[j2 * 8 + dg * 4 + 3] = hp; svl[j2 * 8 + dg * 4 + 3] = lp;
    }

    // Q A-fragments, log2-domain pre-scale, hi/lo split (2 m-tiles per warp)
    const float qscale = 0.35355339059327373f * 1.4426950408889634f;
    u32 qh[2][2], ql[2][2];
    const int m0 = warp * 32;
    {
        const float* qb = g_q + base;
        #pragma unroll
        for (int mt = 0; mt < 2; mt++) {
            int r = m0 + mt * 16 + (lane >> 2);
            float2 f0 = *(const float2*)(qb + r * 8 + (lane & 3) * 2);
            float2 f1 = *(const float2*)(qb + (r + 8) * 8 + (lane & 3) * 2);
            split2(f0.x * qscale, f0.y * qscale, qh[mt][0], ql[mt][0]);
            split2(f1.x * qscale, f1.y * qscale, qh[mt][1], ql[mt][1]);
        }
    }
    __syncthreads();

    float o[2][4];
    float l0[2], l1[2];
    #pragma unroll
    for (int mt = 0; mt < 2; mt++) {
        o[mt][0] = o[mt][1] = o[mt][2] = o[mt][3] = 0.0f;
        l0[mt] = 0.0f; l1[mt] = 0.0f;
    }

    const int vb_idx = (lane & 3) * 8 + (lane >> 2);

    // ---- prologue: scores for chunk 0 ----
    float s[2][8];
    {
        u32 kh0 = skh[lane],      kl0 = skl[lane];
        u32 kh1 = skh[32 + lane], kl1 = skl[32 + lane];
        #pragma unroll
        for (int mt = 0; mt < 2; mt++) {
            float t0[4] = {0, 0, 0, 0}, t1[4] = {0, 0, 0, 0};
            mma16(t0, qh[mt][0], qh[mt][1], ql[mt][0], ql[mt][1], kh0, kh0);
            mma8(t0, qh[mt][0], qh[mt][1], kl0);
            mma16(t1, qh[mt][0], qh[mt][1], ql[mt][0], ql[mt][1], kh1, kh1);
            mma8(t1, qh[mt][0], qh[mt][1], kl1);
            s[mt][0] = t0[0]; s[mt][1] = t0[1]; s[mt][2] = t0[2]; s[mt][3] = t0[3];
            s[mt][4] = t1[0]; s[mt][5] = t1[1]; s[mt][6] = t1[2]; s[mt][7] = t1[3];
        }
    }

    #pragma unroll 1
    for (int j0 = 0; j0 < NSEQ; j0 += 16) {
        // 1) exps for CURRENT chunk — 16 independent MUFU ops, issued first
        float p[2][8];
        #pragma unroll
        for (int mt = 0; mt < 2; mt++)
            #pragma unroll
            for (int e = 0; e < 8; e++)
                p[mt][e] = ex2(s[mt][e]);

        // 2) scores for NEXT chunk (tensor) — independent of the exps above
        const int jn = j0 + 16;
        if (jn < NSEQ) {
            u32 kh0 = skh[jn * 4 + lane],       kl0 = skl[jn * 4 + lane];
            u32 kh1 = skh[(jn + 8) * 4 + lane], kl1 = skl[(jn + 8) * 4 + lane];
            #pragma unroll
            for (int mt = 0; mt < 2; mt++) {
                float t0[4] = {0, 0, 0, 0}, t1[4] = {0, 0, 0, 0};
                mma16(t0, qh[mt][0], qh[mt][1], ql[mt][0], ql[mt][1], kh0, kh0);
                mma8(t0, qh[mt][0], qh[mt][1], kl0);
                mma16(t1, qh[mt][0], qh[mt][1], ql[mt][0], ql[mt][1], kh1, kh1);
                mma8(t1, qh[mt][0], qh[mt][1], kl1);
                s[mt][0] = t0[0]; s[mt][1] = t0[1]; s[mt][2] = t0[2]; s[mt][3] = t0[3];
                s[mt][4] = t1[0]; s[mt][5] = t1[1]; s[mt][6] = t1[2]; s[mt][7] = t1[3];
            }
        }

        // 3) V frags + round P once (consistent denominator) + PV MMAs
        u32 bvh0 = svh[(j0 >> 1) * 8 + vb_idx];
        u32 bvl0 = svl[(j0 >> 1) * 8 + vb_idx];
        u32 bvh1 = svh[(j0 >> 1) * 8 + 32 + vb_idx];
        u32 bvl1 = svl[(j0 >> 1) * 8 + 32 + vb_idx];

        #pragma unroll
        for (int mt = 0; mt < 2; mt++) {
            u32 pah0 = cvt_bf2(p[mt][1], p[mt][0]);
            u32 pbh0 = cvt_bf2(p[mt][3], p[mt][2]);
            u32 pah1 = cvt_bf2(p[mt][5], p[mt][4]);
            u32 pbh1 = cvt_bf2(p[mt][7], p[mt][6]);

            l0[mt] += (bflo(pah0) + bfhi(pah0)) + (bflo(pah1) + bfhi(pah1));
            l1[mt] += (bflo(pbh0) + bfhi(pbh0)) + (bflo(pbh1) + bfhi(pbh1));

            mma16(o[mt], pah0, pbh0, pah1, pbh1, bvh0, bvh1);
            mma16(o[mt], pah0, pbh0, pah1, pbh1, bvl0, bvl1);
        }
    }

    // normalize and write
    #pragma unroll
    for (int mt = 0; mt < 2; mt++) {
        float a = l0[mt], b = l1[mt];
        a += __shfl_xor_sync(0xffffffffu, a, 1);
        a += __shfl_xor_sync(0xffffffffu, a, 2);
        b += __shfl_xor_sync(0xffffffffu, b, 1);
        b += __shfl_xor_sync(0xffffffffu, b, 2);
        float r0 = __fdividef(1.0f, a);
        float r1 = __fdividef(1.0f, b);

        int row = bt * NSEQ + m0 + mt * 16 + (lane >> 2);
        int col = h * HD + (lane & 3) * 2;
        *(float2*)&g_att[row * DMODEL + col]       = make_float2(o[mt][0] * r0, o[mt][1] * r0);
        *(float2*)&g_att[(row + 8) * DMODEL + col] = make_float2(o[mt][2] * r1, o[mt][3] * r1);
    }
}

// ---------------------------------------------------------------------------
// Kernel 3: out = relu(att @ W10 + b10) @ W11 + b11; register-chained GEMMs.
// (R10 proven version)
// ---------------------------------------------------------------------------
__global__ __launch_bounds__(256) void proj_kernel(
    const float* __restrict__ W10, const float* __restrict__ b10,
    const float* __restrict__ W11, const float* __restrict__ b11,
    float* __restrict__ out)
{
    __shared__ __align__(16) u32 sw10h[32 * WPAD];
    __shared__ __align__(16) u32 sw10l[32 * WPAD];
    __shared__ __align__(16) u32 sw11h[32 * WPAD];
    __shared__ __align__(16) u32 sw11l[32 * WPAD];

    const int tid  = threadIdx.x;
    const int lane = tid & 31;
    const int warp = tid >> 5;
    const int gr   = lane >> 2;
    const int kc   = lane & 3;

    #pragma unroll
    for (int e = 0; e < 8; e++) {
        int idx = e * 256 + tid;
        int k2 = idx >> 6, n = idx & 63;
        u32 hp, lp;
        split2(W10[(2 * k2) * 64 + n], W10[(2 * k2 + 1) * 64 + n], hp, lp);
        sw10h[k2 * WPAD + n] = hp;
        sw10l[k2 * WPAD + n] = lp;
        split2(W11[(2 * k2) * 64 + n], W11[(2 * k2 + 1) * 64 + n], hp, lp);
        sw11h[k2 * WPAD + n] = hp;
        sw11l[k2 * WPAD + n] = lp;
    }
    __syncthreads();

    const int r0 = blockIdx.x * 128 + warp * 16 + gr;

    float c1[8][4];
    #pragma unroll
    for (int nt = 0; nt < 8; nt++)
        #pragma unroll
        for (int e = 0; e < 4; e++) c1[nt][e] = 0.0f;

    #pragma unroll
    for (int ks = 0; ks < 8; ks++) {
        const int kk = ks * 8 + kc * 2;
        float2 f0 = *(const float2*)(g_att + r0 * 64 + kk);
        float2 f1 = *(const float2*)(g_att + (r0 + 8) * 64 + kk);
        u32 ah0, al0, ah1, al1;
        split2(f0.x, f0.y, ah0, al0);
        split2(f1.x, f1.y, ah1, al1);
        const u32* bh = &sw10h[(ks * 4 + kc) * WPAD + gr];
        const u32* bl = &sw10l[(ks * 4 + kc) * WPAD + gr];
        #pragma unroll
        for (int nt = 0; nt < 8; nt++) {
            u32 wbh = bh[nt * 8];
            u32 wbl = bl[nt * 8];
            mma16(c1[nt], ah0, ah1, al0, al1, wbh, wbh);
            mma8(c1[nt], ah0, ah1, wbl);
        }
    }

    #pragma unroll
    for (int nt = 0; nt < 8; nt++) {
        float bx = b10[nt * 8 + kc * 2], by = b10[nt * 8 + kc * 2 + 1];
        c1[nt][0] = fmaxf(c1[nt][0] + bx, 0.0f);
        c1[nt][1] = fmaxf(c1[nt][1] + by, 0.0f);
        c1[nt][2] = fmaxf(c1[nt][2] + bx, 0.0f);
        c1[nt][3] = fmaxf(c1[nt][3] + by, 0.0f);
    }

    float c2[8][4];
    #pragma unroll
    for (int nt = 0; nt < 8; nt++)
        #pragma unroll
        for (int e = 0; e < 4; e++) c2[nt][e] = 0.0f;

    #pragma unroll
    for (int ks = 0; ks < 8; ks++) {
        u32 ah0, al0, ah1, al1;
        split2(c1[ks][0], c1[ks][1], ah0, al0);
        split2(c1[ks][2], c1[ks][3], ah1, al1);
        const u32* bh = &sw11h[(ks * 4 + kc) * WPAD + gr];
        const u32* bl = &sw11l[(ks * 4 + kc) * WPAD + gr];
        #pragma unroll
        for (int nt = 0; nt < 8; nt++) {
            u32 wbh = bh[nt * 8];
            u32 wbl = bl[nt * 8];
            mma16(c2[nt], ah0, ah1, al0, al1, wbh, wbh);
            mma8(c2[nt], ah0, ah1, wbl);
        }
    }

    #pragma unroll
    for (int nt = 0; nt < 8; nt++) {
        float bx = b11[nt * 8 + kc * 2], by = b11[nt * 8 + kc * 2 + 1];
        float* dst = out + r0 * 64 + nt * 8 + kc * 2;
        *(float2*)dst            = make_float2(c2[nt][0] + bx, c2[nt][1] + by);
        *(float2*)(dst + 8 * 64) = make_float2(c2[nt][2] + bx, c2[nt][3] + by);
    }
}

// ---------------------------------------------------------------------------
extern "C" void kernel_launch(void* const* d_in, const int* in_sizes, int n_in,
                              void* d_out, int out_size)
{
    const float* X   = (const float*)d_in[0];
    const float* STE = (const float*)d_in[1];
    const float* W7  = (const float*)d_in[2];
    const float* b7  = (const float*)d_in[3];
    const float* W8  = (const float*)d_in[4];
    const float* b8  = (const float*)d_in[5];
    const float* W9  = (const float*)d_in[6];
    const float* b9  = (const float*)d_in[7];
    const float* W10 = (const float*)d_in[8];
    const float* b10 = (const float*)d_in[9];
    const float* W11 = (const float*)d_in[10];
    const float* b11 = (const float*)d_in[11];
    float* out = (float*)d_out;

    qkv_kernel<<<dim3(TOKENS / 128, 3), 256>>>(X, STE, W7, b7, W8, b8, W9, b9);
    attn_kernel<<<dim3(NBT, KH), 512>>>();
    proj_kernel<<<TOKENS / 128, 256>>>(W10, b10, W11, b11, out);
}

// round 14
// speedup vs baseline: 1.3861x; 1.3861x over previous
#include <cuda_runtime.h>

// Problem constants
#define NBT   96      // B*T
#define NSEQ  512     // N
#define DMODEL 64
#define KH    8
#define HD    8
#define TOKENS (NBT * NSEQ)   // 49152

typedef unsigned long long u64;
typedef unsigned int u32;

// Scratch: q,k,v row-major [h][bt][n][d]; att [tok][64]
__device__ float g_q[KH * NBT * NSEQ * HD];
__device__ float g_k[KH * NBT * NSEQ * HD];
__device__ float g_v[KH * NBT * NSEQ * HD];
__device__ float g_att[TOKENS * DMODEL];

// ---------------- bf16 helpers (qkv/proj, proven) ----------------
__device__ __forceinline__ u32 cvt_bf2(float x1, float x0) {
    u32 r; asm("cvt.rn.bf16x2.f32 %0, %1, %2;" : "=r"(r) : "f"(x1), "f"(x0)); return r;
}
__device__ __forceinline__ float bflo(u32 p) { return __uint_as_float(p << 16); }
__device__ __forceinline__ float bfhi(u32 p) { return __uint_as_float(p & 0xffff0000u); }
__device__ __forceinline__ void split2(float x0, float x1, u32& hp, u32& lp) {
    hp = cvt_bf2(x1, x0);
    lp = cvt_bf2(x1 - bfhi(hp), x0 - bflo(hp));
}

// ---------------- f16 helpers (attention) ----------------
// pack {lo16 = f16(x0), hi16 = f16(x1)}
__device__ __forceinline__ u32 cvt_h2(float x1, float x0) {
    u32 r; asm("cvt.rn.f16x2.f32 %0, %1, %2;" : "=r"(r) : "f"(x1), "f"(x0)); return r;
}
__device__ __forceinline__ void h2_to_f32(u32 p, float& lo, float& hi) {
    asm("{\n\t.reg .f16 l, h;\n\tmov.b32 {l, h}, %2;\n\t"
        "cvt.f32.f16 %0, l;\n\tcvt.f32.f16 %1, h;\n\t}"
        : "=f"(lo), "=f"(hi) : "r"(p));
}
__device__ __forceinline__ void split2h(float x0, float x1, u32& hp, u32& lp) {
    hp = cvt_h2(x1, x0);
    float e0, e1; h2_to_f32(hp, e0, e1);
    lp = cvt_h2(x1 - e1, x0 - e0);
}
__device__ __forceinline__ u32 ex2h2(u32 x) {
    u32 y; asm("ex2.approx.f16x2 %0, %1;" : "=r"(y) : "r"(x)); return y;
}
__device__ __forceinline__ u32 hadd2(u32 a, u32 b) {
    u32 d; asm("add.rn.f16x2 %0, %1, %2;" : "=r"(d) : "r"(a), "r"(b)); return d;
}

// ---------------- MMA wrappers ----------------
// bf16 variants (qkv/proj)
__device__ __forceinline__ void mma8(float (&d)[4], u32 a0, u32 a1, u32 b) {
    asm("mma.sync.aligned.m16n8k8.row.col.f32.bf16.bf16.f32 "
        "{%0,%1,%2,%3},{%4,%5},{%6},{%0,%1,%2,%3};"
        : "+f"(d[0]), "+f"(d[1]), "+f"(d[2]), "+f"(d[3])
        : "r"(a0), "r"(a1), "r"(b));
}
__device__ __forceinline__ void mma16(float (&d)[4], u32 a0, u32 a1, u32 a2, u32 a3,
                                      u32 b0, u32 b1) {
    asm("mma.sync.aligned.m16n8k16.row.col.f32.bf16.bf16.f32 "
        "{%0,%1,%2,%3},{%4,%5,%6,%7},{%8,%9},{%0,%1,%2,%3};"
        : "+f"(d[0]), "+f"(d[1]), "+f"(d[2]), "+f"(d[3])
        : "r"(a0), "r"(a1), "r"(a2), "r"(a3), "r"(b0), "r"(b1));
}
// f16 variants (attention)
__device__ __forceinline__ void mma8f(float (&d)[4], u32 a0, u32 a1, u32 b) {
    asm("mma.sync.aligned.m16n8k8.row.col.f32.f16.f16.f32 "
        "{%0,%1,%2,%3},{%4,%5},{%6},{%0,%1,%2,%3};"
        : "+f"(d[0]), "+f"(d[1]), "+f"(d[2]), "+f"(d[3])
        : "r"(a0), "r"(a1), "r"(b));
}
__device__ __forceinline__ void mma16f(float (&d)[4], u32 a0, u32 a1, u32 a2, u32 a3,
                                       u32 b0, u32 b1) {
    asm("mma.sync.aligned.m16n8k16.row.col.f32.f16.f16.f32 "
        "{%0,%1,%2,%3},{%4,%5,%6,%7},{%8,%9},{%0,%1,%2,%3};"
        : "+f"(d[0]), "+f"(d[1]), "+f"(d[2]), "+f"(d[3])
        : "r"(a0), "r"(a1), "r"(a2), "r"(a3), "r"(b0), "r"(b1));
}

#define WPAD 72   // row stride for weight smem planes — proven conflict-free

// ---------------------------------------------------------------------------
// Kernel 1: fused QKV projection on tensor cores (R10 proven version, bf16).
// ---------------------------------------------------------------------------
__global__ __launch_bounds__(256) void qkv_kernel(
    const float* __restrict__ X, const float* __restrict__ STE,
    const float* __restrict__ W7, const float* __restrict__ b7,
    const float* __restrict__ W8, const float* __restrict__ b8,
    const float* __restrict__ W9, const float* __restrict__ b9)
{
    __shared__ __align__(16) u32 swh[64 * WPAD];
    __shared__ __align__(16) u32 swl[64 * WPAD];

    const int mat = blockIdx.y;
    const float* W  = (mat == 0) ? W7 : (mat == 1) ? W8 : W9;
    const float* bv = (mat == 0) ? b7 : (mat == 1) ? b8 : b9;
    float* gout     = (mat == 0) ? g_q : (mat == 1) ? g_k : g_v;

    const int tid  = threadIdx.x;
    const int lane = tid & 31;
    const int warp = tid >> 5;
    const int row0 = blockIdx.x * 128;
    const int bt   = row0 >> 9;
    const int n0b  = row0 & 511;
    const int gr   = lane >> 2;
    const int kc   = lane & 3;

    #pragma unroll
    for (int e = 0; e < 16; e++) {
        int idx = e * 256 + tid;
        int k2 = idx >> 6, n = idx & 63;
        float w0 = W[(2 * k2) * 64 + n];
        float w1 = W[(2 * k2 + 1) * 64 + n];
        u32 hp, lp;
        split2(w0, w1, hp, lp);
        swh[k2 * WPAD + n] = hp;
        swl[k2 * WPAD + n] = lp;
    }
    __syncthreads();

    float c[8][4];
    #pragma unroll
    for (int nt = 0; nt < 8; nt++)
        #pragma unroll
        for (int e = 0; e < 4; e++) c[nt][e] = 0.0f;

    const int r0 = row0 + warp * 16 + gr;

    #pragma unroll 1
    for (int ks = 0; ks < 16; ks++) {
        const float* src = (ks < 8) ? X : STE;
        const int kk = (ks & 7) * 8 + kc * 2;
        float2 f0 = *(const float2*)(src + r0 * 64 + kk);
        float2 f1 = *(const float2*)(src + (r0 + 8) * 64 + kk);
        u32 ah0, al0, ah1, al1;
        split2(f0.x, f0.y, ah0, al0);
        split2(f1.x, f1.y, ah1, al1);

        const u32* bh = &swh[(ks * 4 + kc) * WPAD + gr];
        const u32* bl = &swl[(ks * 4 + kc) * WPAD + gr];
        #pragma unroll
        for (int nt = 0; nt < 8; nt++) {
            u32 wbh = bh[nt * 8];
            u32 wbl = bl[nt * 8];
            mma16(c[nt], ah0, ah1, al0, al1, wbh, wbh);
            mma8(c[nt], ah0, ah1, wbl);
        }
    }

    const int n_lo = n0b + warp * 16 + gr;
    #pragma unroll
    for (int nt = 0; nt < 8; nt++) {
        const int d0 = kc * 2;
        float bx = bv[nt * 8 + d0], by = bv[nt * 8 + d0 + 1];
        float2 oA = make_float2(fmaxf(c[nt][0] + bx, 0.0f), fmaxf(c[nt][1] + by, 0.0f));
        float2 oB = make_float2(fmaxf(c[nt][2] + bx, 0.0f), fmaxf(c[nt][3] + by, 0.0f));
        float* dst = &gout[(((nt * NBT) + bt) * NSEQ + n_lo) * HD + d0];
        *(float2*)dst            = oA;
        *(float2*)(dst + 8 * HD) = oB;
    }
}

// ---------------------------------------------------------------------------
// Kernel 2: attention per (bt, head), f16 datapath. 16 warps x 32 rows.
// ex2.approx.f16x2 computes 2 exps per MUFU op AND its output is directly the
// f16 PV A-fragment. V staged as single f16 (rounding averages out). Scores:
// 3-term f16 split. Consistent denominator from the same f16 p-hat values.
// grid (96, 8), 512 threads.
// ---------------------------------------------------------------------------
__global__ __launch_bounds__(512) void attn_kernel()
{
    __shared__ __align__(16) u32 skh[NSEQ * 4];       // K f16 hi pairs [j][c]
    __shared__ __align__(16) u32 skl[NSEQ * 4];       // K f16 lo pairs
    __shared__ __align__(16) u32 svh[(NSEQ / 2) * 8]; // V f16 pairs [j2][d]

    const int bt   = blockIdx.x;
    const int h    = blockIdx.y;
    const int tid  = threadIdx.x;
    const int lane = tid & 31;
    const int warp = tid >> 5;
    const int base = (h * NBT + bt) * NSEQ * HD;

    // stage K -> f16 hi/lo pairs over d (one row per thread)
    {
        int r = tid;
        const float4* kp = (const float4*)(g_k + base + r * 8);
        float4 f0 = kp[0], f1 = kp[1];
        u32 h0, l0, h1, l1, h2, l2, h3, l3;
        split2h(f0.x, f0.y, h0, l0);
        split2h(f0.z, f0.w, h1, l1);
        split2h(f1.x, f1.y, h2, l2);
        split2h(f1.z, f1.w, h3, l3);
        *(uint4*)&skh[r * 4] = make_uint4(h0, h1, h2, h3);
        *(uint4*)&skl[r * 4] = make_uint4(l0, l1, l2, l3);
    }

    // stage V -> f16 pairs over j at fixed d (one (j2, d-group) per thread)
    {
        int j2 = tid & 255, dg = tid >> 8;
        const float* vb = g_v + base + (2 * j2) * 8 + dg * 4;
        float4 f0 = *(const float4*)vb;        // row 2*j2
        float4 f1 = *(const float4*)(vb + 8);  // row 2*j2+1
        svh[j2 * 8 + dg * 4 + 0] = cvt_h2(f1.x, f0.x);
        svh[j2 * 8 + dg * 4 + 1] = cvt_h2(f1.y, f0.y);
        svh[j2 * 8 + dg * 4 + 2] = cvt_h2(f1.z, f0.z);
        svh[j2 * 8 + dg * 4 + 3] = cvt_h2(f1.w, f0.w);
    }

    // Q A-fragments, log2-domain pre-scale, f16 hi/lo split (2 m-tiles/warp)
    const float qscale = 0.35355339059327373f * 1.4426950408889634f;
    u32 qh[2][2], ql[2][2];
    const int m0 = warp * 32;
    {
        const float* qb = g_q + base;
        #pragma unroll
        for (int mt = 0; mt < 2; mt++) {
            int r = m0 + mt * 16 + (lane >> 2);
            float2 f0 = *(const float2*)(qb + r * 8 + (lane & 3) * 2);
            float2 f1 = *(const float2*)(qb + (r + 8) * 8 + (lane & 3) * 2);
            split2h(f0.x * qscale, f0.y * qscale, qh[mt][0], ql[mt][0]);
            split2h(f1.x * qscale, f1.y * qscale, qh[mt][1], ql[mt][1]);
        }
    }
    __syncthreads();

    float o[2][4];
    float l0[2], l1[2];
    #pragma unroll
    for (int mt = 0; mt < 2; mt++) {
        o[mt][0] = o[mt][1] = o[mt][2] = o[mt][3] = 0.0f;
        l0[mt] = 0.0f; l1[mt] = 0.0f;
    }

    const int vb_idx = (lane & 3) * 8 + (lane >> 2);

    #pragma unroll 1
    for (int j0 = 0; j0 < NSEQ; j0 += 16) {
        u32 bkh0 = skh[j0 * 4 + lane];
        u32 bkl0 = skl[j0 * 4 + lane];
        u32 bkh1 = skh[(j0 + 8) * 4 + lane];
        u32 bkl1 = skl[(j0 + 8) * 4 + lane];
        u32 bvh0 = svh[(j0 >> 1) * 8 + vb_idx];
        u32 bvh1 = svh[(j0 >> 1) * 8 + 32 + vb_idx];

        #pragma unroll
        for (int mt = 0; mt < 2; mt++) {
            // scores (3-term f16 split, k16-folded)
            float s0[4] = {0, 0, 0, 0}, s1[4] = {0, 0, 0, 0};
            mma16f(s0, qh[mt][0], qh[mt][1], ql[mt][0], ql[mt][1], bkh0, bkh0);
            mma8f(s0, qh[mt][0], qh[mt][1], bkl0);
            mma16f(s1, qh[mt][0], qh[mt][1], ql[mt][0], ql[mt][1], bkh1, bkh1);
            mma8f(s1, qh[mt][0], qh[mt][1], bkl1);

            // pack scores to f16x2 and exp: 1 MUFU op per TWO exps; the
            // result is directly the f16 A-fragment for the PV MMA.
            u32 pa0 = ex2h2(cvt_h2(s0[1], s0[0]));
            u32 pb0 = ex2h2(cvt_h2(s0[3], s0[2]));
            u32 pa1 = ex2h2(cvt_h2(s1[1], s1[0]));
            u32 pb1 = ex2h2(cvt_h2(s1[3], s1[2]));

            // consistent denominator from the same f16 p-hat values
            u32 t0 = hadd2(pa0, pa1);
            u32 t1 = hadd2(pb0, pb1);
            float e0, e1;
            h2_to_f32(t0, e0, e1); l0[mt] += e0 + e1;
            h2_to_f32(t1, e0, e1); l1[mt] += e0 + e1;

            // PV: single f16 mma16 over 16 j's
            mma16f(o[mt], pa0, pb0, pa1, pb1, bvh0, bvh1);
        }
    }

    // normalize and write
    #pragma unroll
    for (int mt = 0; mt < 2; mt++) {
        float a = l0[mt], b = l1[mt];
        a += __shfl_xor_sync(0xffffffffu, a, 1);
        a += __shfl_xor_sync(0xffffffffu, a, 2);
        b += __shfl_xor_sync(0xffffffffu, b, 1);
        b += __shfl_xor_sync(0xffffffffu, b, 2);
        float r0 = __fdividef(1.0f, a);
        float r1 = __fdividef(1.0f, b);

        int row = bt * NSEQ + m0 + mt * 16 + (lane >> 2);
        int col = h * HD + (lane & 3) * 2;
        *(float2*)&g_att[row * DMODEL + col]       = make_float2(o[mt][0] * r0, o[mt][1] * r0);
        *(float2*)&g_att[(row + 8) * DMODEL + col] = make_float2(o[mt][2] * r1, o[mt][3] * r1);
    }
}

// ---------------------------------------------------------------------------
// Kernel 3: out = relu(att @ W10 + b10) @ W11 + b11; register-chained GEMMs.
// (R10 proven version, bf16)
// ---------------------------------------------------------------------------
__global__ __launch_bounds__(256) void proj_kernel(
    const float* __restrict__ W10, const float* __restrict__ b10,
    const float* __restrict__ W11, const float* __restrict__ b11,
    float* __restrict__ out)
{
    __shared__ __align__(16) u32 sw10h[32 * WPAD];
    __shared__ __align__(16) u32 sw10l[32 * WPAD];
    __shared__ __align__(16) u32 sw11h[32 * WPAD];
    __shared__ __align__(16) u32 sw11l[32 * WPAD];

    const int tid  = threadIdx.x;
    const int lane = tid & 31;
    const int warp = tid >> 5;
    const int gr   = lane >> 2;
    const int kc   = lane & 3;

    #pragma unroll
    for (int e = 0; e < 8; e++) {
        int idx = e * 256 + tid;
        int k2 = idx >> 6, n = idx & 63;
        u32 hp, lp;
        split2(W10[(2 * k2) * 64 + n], W10[(2 * k2 + 1) * 64 + n], hp, lp);
        sw10h[k2 * WPAD + n] = hp;
        sw10l[k2 * WPAD + n] = lp;
        split2(W11[(2 * k2) * 64 + n], W11[(2 * k2 + 1) * 64 + n], hp, lp);
        sw11h[k2 * WPAD + n] = hp;
        sw11l[k2 * WPAD + n] = lp;
    }
    __syncthreads();

    const int r0 = blockIdx.x * 128 + warp * 16 + gr;

    float c1[8][4];
    #pragma unroll
    for (int nt = 0; nt < 8; nt++)
        #pragma unroll
        for (int e = 0; e < 4; e++) c1[nt][e] = 0.0f;

    #pragma unroll
    for (int ks = 0; ks < 8; ks++) {
        const int kk = ks * 8 + kc * 2;
        float2 f0 = *(const float2*)(g_att + r0 * 64 + kk);
        float2 f1 = *(const float2*)(g_att + (r0 + 8) * 64 + kk);
        u32 ah0, al0, ah1, al1;
        split2(f0.x, f0.y, ah0, al0);
        split2(f1.x, f1.y, ah1, al1);
        const u32* bh = &sw10h[(ks * 4 + kc) * WPAD + gr];
        const u32* bl = &sw10l[(ks * 4 + kc) * WPAD + gr];
        #pragma unroll
        for (int nt = 0; nt < 8; nt++) {
            u32 wbh = bh[nt * 8];
            u32 wbl = bl[nt * 8];
            mma16(c1[nt], ah0, ah1, al0, al1, wbh, wbh);
            mma8(c1[nt], ah0, ah1, wbl);
        }
    }

    #pragma unroll
    for (int nt = 0; nt < 8; nt++) {
        float bx = b10[nt * 8 + kc * 2], by = b10[nt * 8 + kc * 2 + 1];
        c1[nt][0] = fmaxf(c1[nt][0] + bx, 0.0f);
        c1[nt][1] = fmaxf(c1[nt][1] + by, 0.0f);
        c1[nt][2] = fmaxf(c1[nt][2] + bx, 0.0f);
        c1[nt][3] = fmaxf(c1[nt][3] + by, 0.0f);
    }

    float c2[8][4];
    #pragma unroll
    for (int nt = 0; nt < 8; nt++)
        #pragma unroll
        for (int e = 0; e < 4; e++) c2[nt][e] = 0.0f;

    #pragma unroll
    for (int ks = 0; ks < 8; ks++) {
        u32 ah0, al0, ah1, al1;
        split2(c1[ks][0], c1[ks][1], ah0, al0);
        split2(c1[ks][2], c1[ks][3], ah1, al1);
        const u32* bh = &sw11h[(ks * 4 + kc) * WPAD + gr];
        const u32* bl = &sw11l[(ks * 4 + kc) * WPAD + gr];
        #pragma unroll
        for (int nt = 0; nt < 8; nt++) {
            u32 wbh = bh[nt * 8];
            u32 wbl = bl[nt * 8];
            mma16(c2[nt], ah0, ah1, al0, al1, wbh, wbh);
            mma8(c2[nt], ah0, ah1, wbl);
        }
    }

    #pragma unroll
    for (int nt = 0; nt < 8; nt++) {
        float bx = b11[nt * 8 + kc * 2], by = b11[nt * 8 + kc * 2 + 1];
        float* dst = out + r0 * 64 + nt * 8 + kc * 2;
        *(float2*)dst            = make_float2(c2[nt][0] + bx, c2[nt][1] + by);
        *(float2*)(dst + 8 * 64) = make_float2(c2[nt][2] + bx, c2[nt][3] + by);
    }
}

// ---------------------------------------------------------------------------
extern "C" void kernel_launch(void* const* d_in, const int* in_sizes, int n_in,
                              void* d_out, int out_size)
{
    const float* X   = (const float*)d_in[0];
    const float* STE = (const float*)d_in[1];
    const float* W7  = (const float*)d_in[2];
    const float* b7  = (const float*)d_in[3];
    const float* W8  = (const float*)d_in[4];
    const float* b8  = (const float*)d_in[5];
    const float* W9  = (const float*)d_in[6];
    const float* b9  = (const float*)d_in[7];
    const float* W10 = (const float*)d_in[8];
    const float* b10 = (const float*)d_in[9];
    const float* W11 = (const float*)d_in[10];
    const float* b11 = (const float*)d_in[11];
    float* out = (float*)d_out;

    qkv_kernel<<<dim3(TOKENS / 128, 3), 256>>>(X, STE, W7, b7, W8, b8, W9, b9);
    attn_kernel<<<dim3(NBT, KH), 512>>>();
    proj_kernel<<<TOKENS / 128, 256>>>(W10, b10, W11, b11, out);
}

// round 15
// speedup vs baseline: 1.7396x; 1.2550x over previous
#include <cuda_runtime.h>

// Problem constants
#define NBT   96      // B*T
#define NSEQ  512     // N
#define DMODEL 64
#define KH    8
#define HD    8
#define TOKENS (NBT * NSEQ)   // 49152

typedef unsigned long long u64;
typedef unsigned int u32;

// Scratch: q,k,v row-major [h][bt][n][d]; att [tok][64]
__device__ float g_q[KH * NBT * NSEQ * HD];
__device__ float g_k[KH * NBT * NSEQ * HD];
__device__ float g_v[KH * NBT * NSEQ * HD];
__device__ float g_att[TOKENS * DMODEL];

// ---------------- f16 helpers ----------------
// pack {lo16 = f16(x0), hi16 = f16(x1)}
__device__ __forceinline__ u32 cvt_h2(float x1, float x0) {
    u32 r; asm("cvt.rn.f16x2.f32 %0, %1, %2;" : "=r"(r) : "f"(x1), "f"(x0)); return r;
}
__device__ __forceinline__ void h2_to_f32(u32 p, float& lo, float& hi) {
    asm("{\n\t.reg .f16 l, h;\n\tmov.b32 {l, h}, %2;\n\t"
        "cvt.f32.f16 %0, l;\n\tcvt.f32.f16 %1, h;\n\t}"
        : "=f"(lo), "=f"(hi) : "r"(p));
}
__device__ __forceinline__ void split2h(float x0, float x1, u32& hp, u32& lp) {
    hp = cvt_h2(x1, x0);
    float e0, e1; h2_to_f32(hp, e0, e1);
    lp = cvt_h2(x1 - e1, x0 - e0);
}
__device__ __forceinline__ u32 ex2h2(u32 x) {
    u32 y; asm("ex2.approx.f16x2 %0, %1;" : "=r"(y) : "r"(x)); return y;
}
__device__ __forceinline__ u32 hadd2(u32 a, u32 b) {
    u32 d; asm("add.rn.f16x2 %0, %1, %2;" : "=r"(d) : "r"(a), "r"(b)); return d;
}

// ---------------- f16 MMA wrappers ----------------
__device__ __forceinline__ void mma8f(float (&d)[4], u32 a0, u32 a1, u32 b) {
    asm("mma.sync.aligned.m16n8k8.row.col.f32.f16.f16.f32 "
        "{%0,%1,%2,%3},{%4,%5},{%6},{%0,%1,%2,%3};"
        : "+f"(d[0]), "+f"(d[1]), "+f"(d[2]), "+f"(d[3])
        : "r"(a0), "r"(a1), "r"(b));
}
__device__ __forceinline__ void mma16f(float (&d)[4], u32 a0, u32 a1, u32 a2, u32 a3,
                                       u32 b0, u32 b1) {
    asm("mma.sync.aligned.m16n8k16.row.col.f32.f16.f16.f32 "
        "{%0,%1,%2,%3},{%4,%5,%6,%7},{%8,%9},{%0,%1,%2,%3};"
        : "+f"(d[0]), "+f"(d[1]), "+f"(d[2]), "+f"(d[3])
        : "r"(a0), "r"(a1), "r"(a2), "r"(a3), "r"(b0), "r"(b1));
}

#define WPAD 72   // row stride for weight smem planes — proven conflict-free

// ---------------------------------------------------------------------------
// Kernel 1: fused QKV projection, f16 2-term: A single f16 (split dropped),
// W kept as hi/lo planes; one mma16f per (ks,nt) computes a·(wh+wl) = a·w,
// dropping only the al·w residual (~2^-12 relative).
// grid (384, 3), 256 threads; outputs row-major [h][bt][n][d].
// ---------------------------------------------------------------------------
__global__ __launch_bounds__(256) void qkv_kernel(
    const float* __restrict__ X, const float* __restrict__ STE,
    const float* __restrict__ W7, const float* __restrict__ b7,
    const float* __restrict__ W8, const float* __restrict__ b8,
    const float* __restrict__ W9, const float* __restrict__ b9)
{
    __shared__ __align__(16) u32 swh[64 * WPAD];
    __shared__ __align__(16) u32 swl[64 * WPAD];

    const int mat = blockIdx.y;
    const float* W  = (mat == 0) ? W7 : (mat == 1) ? W8 : W9;
    const float* bv = (mat == 0) ? b7 : (mat == 1) ? b8 : b9;
    float* gout     = (mat == 0) ? g_q : (mat == 1) ? g_k : g_v;

    const int tid  = threadIdx.x;
    const int lane = tid & 31;
    const int warp = tid >> 5;
    const int row0 = blockIdx.x * 128;
    const int bt   = row0 >> 9;
    const int n0b  = row0 & 511;
    const int gr   = lane >> 2;
    const int kc   = lane & 3;

    #pragma unroll
    for (int e = 0; e < 16; e++) {
        int idx = e * 256 + tid;
        int k2 = idx >> 6, n = idx & 63;
        float w0 = W[(2 * k2) * 64 + n];
        float w1 = W[(2 * k2 + 1) * 64 + n];
        u32 hp, lp;
        split2h(w0, w1, hp, lp);
        swh[k2 * WPAD + n] = hp;
        swl[k2 * WPAD + n] = lp;
    }
    __syncthreads();

    float c[8][4];
    #pragma unroll
    for (int nt = 0; nt < 8; nt++)
        #pragma unroll
        for (int e = 0; e < 4; e++) c[nt][e] = 0.0f;

    const int r0 = row0 + warp * 16 + gr;

    #pragma unroll 1
    for (int ks = 0; ks < 16; ks++) {
        const float* src = (ks < 8) ? X : STE;
        const int kk = (ks & 7) * 8 + kc * 2;
        float2 f0 = *(const float2*)(src + r0 * 64 + kk);
        float2 f1 = *(const float2*)(src + (r0 + 8) * 64 + kk);
        u32 ah0 = cvt_h2(f0.y, f0.x);
        u32 ah1 = cvt_h2(f1.y, f1.x);

        const u32* bh = &swh[(ks * 4 + kc) * WPAD + gr];
        const u32* bl = &swl[(ks * 4 + kc) * WPAD + gr];
        #pragma unroll
        for (int nt = 0; nt < 8; nt++) {
            u32 wbh = bh[nt * 8];
            u32 wbl = bl[nt * 8];
            // a·wh (k0..7) + a·wl (k8..15)  ==  a·w
            mma16f(c[nt], ah0, ah1, ah0, ah1, wbh, wbl);
        }
    }

    const int n_lo = n0b + warp * 16 + gr;
    #pragma unroll
    for (int nt = 0; nt < 8; nt++) {
        const int d0 = kc * 2;
        float bx = bv[nt * 8 + d0], by = bv[nt * 8 + d0 + 1];
        float2 oA = make_float2(fmaxf(c[nt][0] + bx, 0.0f), fmaxf(c[nt][1] + by, 0.0f));
        float2 oB = make_float2(fmaxf(c[nt][2] + bx, 0.0f), fmaxf(c[nt][3] + by, 0.0f));
        float* dst = &gout[(((nt * NBT) + bt) * NSEQ + n_lo) * HD + d0];
        *(float2*)dst            = oA;
        *(float2*)(dst + 8 * HD) = oB;
    }
}

// ---------------------------------------------------------------------------
// Kernel 2: attention per (bt, head), all-f16. Scores: single-f16 q,k, one
// mma8f per 8-j chunk (|s| is small so f16 rounding is ~1e-4-level). Exp via
// ex2.approx.f16x2 (2 exps/MUFU op, output directly PV A-frag). V single f16.
// Consistent denominator. grid (96, 8), 512 threads (16 warps x 32 rows).
// ---------------------------------------------------------------------------
__global__ __launch_bounds__(512) void attn_kernel()
{
    __shared__ __align__(16) u32 skh[NSEQ * 4];       // K f16 pairs [j][c]
    __shared__ __align__(16) u32 svh[(NSEQ / 2) * 8]; // V f16 pairs [j2][d]

    const int bt   = blockIdx.x;
    const int h    = blockIdx.y;
    const int tid  = threadIdx.x;
    const int lane = tid & 31;
    const int warp = tid >> 5;
    const int base = (h * NBT + bt) * NSEQ * HD;

    // stage K -> single f16 pairs over d (one row per thread)
    {
        int r = tid;
        const float4* kp = (const float4*)(g_k + base + r * 8);
        float4 f0 = kp[0], f1 = kp[1];
        *(uint4*)&skh[r * 4] = make_uint4(
            cvt_h2(f0.y, f0.x), cvt_h2(f0.w, f0.z),
            cvt_h2(f1.y, f1.x), cvt_h2(f1.w, f1.z));
    }

    // stage V -> f16 pairs over j at fixed d (one (j2, d-group) per thread)
    {
        int j2 = tid & 255, dg = tid >> 8;
        const float* vb = g_v + base + (2 * j2) * 8 + dg * 4;
        float4 f0 = *(const float4*)vb;        // row 2*j2
        float4 f1 = *(const float4*)(vb + 8);  // row 2*j2+1
        svh[j2 * 8 + dg * 4 + 0] = cvt_h2(f1.x, f0.x);
        svh[j2 * 8 + dg * 4 + 1] = cvt_h2(f1.y, f0.y);
        svh[j2 * 8 + dg * 4 + 2] = cvt_h2(f1.z, f0.z);
        svh[j2 * 8 + dg * 4 + 3] = cvt_h2(f1.w, f0.w);
    }

    // Q A-fragments, log2-domain pre-scale, single f16 (2 m-tiles/warp)
    const float qscale = 0.35355339059327373f * 1.4426950408889634f;
    u32 qh[2][2];
    const int m0 = warp * 32;
    {
        const float* qb = g_q + base;
        #pragma unroll
        for (int mt = 0; mt < 2; mt++) {
            int r = m0 + mt * 16 + (lane >> 2);
            float2 f0 = *(const float2*)(qb + r * 8 + (lane & 3) * 2);
            float2 f1 = *(const float2*)(qb + (r + 8) * 8 + (lane & 3) * 2);
            qh[mt][0] = cvt_h2(f0.y * qscale, f0.x * qscale);
            qh[mt][1] = cvt_h2(f1.y * qscale, f1.x * qscale);
        }
    }
    __syncthreads();

    float o[2][4];
    float l0[2], l1[2];
    #pragma unroll
    for (int mt = 0; mt < 2; mt++) {
        o[mt][0] = o[mt][1] = o[mt][2] = o[mt][3] = 0.0f;
        l0[mt] = 0.0f; l1[mt] = 0.0f;
    }

    const int vb_idx = (lane & 3) * 8 + (lane >> 2);

    #pragma unroll 1
    for (int j0 = 0; j0 < NSEQ; j0 += 16) {
        u32 bkh0 = skh[j0 * 4 + lane];
        u32 bkh1 = skh[(j0 + 8) * 4 + lane];
        u32 bvh0 = svh[(j0 >> 1) * 8 + vb_idx];
        u32 bvh1 = svh[(j0 >> 1) * 8 + 32 + vb_idx];

        #pragma unroll
        for (int mt = 0; mt < 2; mt++) {
            // scores: single-f16 q,k — one mma8 per 8-j chunk
            float s0[4] = {0, 0, 0, 0}, s1[4] = {0, 0, 0, 0};
            mma8f(s0, qh[mt][0], qh[mt][1], bkh0);
            mma8f(s1, qh[mt][0], qh[mt][1], bkh1);

            // pack scores to f16x2 and exp (MUFU; 2 exps/op); result is
            // directly the f16 A-fragment for the PV MMA.
            u32 pa0 = ex2h2(cvt_h2(s0[1], s0[0]));
            u32 pb0 = ex2h2(cvt_h2(s0[3], s0[2]));
            u32 pa1 = ex2h2(cvt_h2(s1[1], s1[0]));
            u32 pb1 = ex2h2(cvt_h2(s1[3], s1[2]));

            // consistent denominator from the same f16 p-hat values
            u32 t0 = hadd2(pa0, pa1);
            u32 t1 = hadd2(pb0, pb1);
            float e0, e1;
            h2_to_f32(t0, e0, e1); l0[mt] += e0 + e1;
            h2_to_f32(t1, e0, e1); l1[mt] += e0 + e1;

            // PV: single f16 mma16 over 16 j's
            mma16f(o[mt], pa0, pb0, pa1, pb1, bvh0, bvh1);
        }
    }

    // normalize and write
    #pragma unroll
    for (int mt = 0; mt < 2; mt++) {
        float a = l0[mt], b = l1[mt];
        a += __shfl_xor_sync(0xffffffffu, a, 1);
        a += __shfl_xor_sync(0xffffffffu, a, 2);
        b += __shfl_xor_sync(0xffffffffu, b, 1);
        b += __shfl_xor_sync(0xffffffffu, b, 2);
        float r0 = __fdividef(1.0f, a);
        float r1 = __fdividef(1.0f, b);

        int row = bt * NSEQ + m0 + mt * 16 + (lane >> 2);
        int col = h * HD + (lane & 3) * 2;
        *(float2*)&g_att[row * DMODEL + col]       = make_float2(o[mt][0] * r0, o[mt][1] * r0);
        *(float2*)&g_att[(row + 8) * DMODEL + col] = make_float2(o[mt][2] * r1, o[mt][3] * r1);
    }
}

// ---------------------------------------------------------------------------
// Kernel 3: out = relu(att @ W10 + b10) @ W11 + b11; f16 2-term on both GEMMs
// (A single f16, W hi/lo planes, one mma16f per step); register-chained.
// grid 384, 256 threads.
// ---------------------------------------------------------------------------
__global__ __launch_bounds__(256) void proj_kernel(
    const float* __restrict__ W10, const float* __restrict__ b10,
    const float* __restrict__ W11, const float* __restrict__ b11,
    float* __restrict__ out)
{
    __shared__ __align__(16) u32 sw10h[32 * WPAD];
    __shared__ __align__(16) u32 sw10l[32 * WPAD];
    __shared__ __align__(16) u32 sw11h[32 * WPAD];
    __shared__ __align__(16) u32 sw11l[32 * WPAD];

    const int tid  = threadIdx.x;
    const int lane = tid & 31;
    const int warp = tid >> 5;
    const int gr   = lane >> 2;
    const int kc   = lane & 3;

    #pragma unroll
    for (int e = 0; e < 8; e++) {
        int idx = e * 256 + tid;
        int k2 = idx >> 6, n = idx & 63;
        u32 hp, lp;
        split2h(W10[(2 * k2) * 64 + n], W10[(2 * k2 + 1) * 64 + n], hp, lp);
        sw10h[k2 * WPAD + n] = hp;
        sw10l[k2 * WPAD + n] = lp;
        split2h(W11[(2 * k2) * 64 + n], W11[(2 * k2 + 1) * 64 + n], hp, lp);
        sw11h[k2 * WPAD + n] = hp;
        sw11l[k2 * WPAD + n] = lp;
    }
    __syncthreads();

    const int r0 = blockIdx.x * 128 + warp * 16 + gr;

    float c1[8][4];
    #pragma unroll
    for (int nt = 0; nt < 8; nt++)
        #pragma unroll
        for (int e = 0; e < 4; e++) c1[nt][e] = 0.0f;

    #pragma unroll
    for (int ks = 0; ks < 8; ks++) {
        const int kk = ks * 8 + kc * 2;
        float2 f0 = *(const float2*)(g_att + r0 * 64 + kk);
        float2 f1 = *(const float2*)(g_att + (r0 + 8) * 64 + kk);
        u32 ah0 = cvt_h2(f0.y, f0.x);
        u32 ah1 = cvt_h2(f1.y, f1.x);
        const u32* bh = &sw10h[(ks * 4 + kc) * WPAD + gr];
        const u32* bl = &sw10l[(ks * 4 + kc) * WPAD + gr];
        #pragma unroll
        for (int nt = 0; nt < 8; nt++) {
            mma16f(c1[nt], ah0, ah1, ah0, ah1, bh[nt * 8], bl[nt * 8]);
        }
    }

    #pragma unroll
    for (int nt = 0; nt < 8; nt++) {
        float bx = b10[nt * 8 + kc * 2], by = b10[nt * 8 + kc * 2 + 1];
        c1[nt][0] = fmaxf(c1[nt][0] + bx, 0.0f);
        c1[nt][1] = fmaxf(c1[nt][1] + by, 0.0f);
        c1[nt][2] = fmaxf(c1[nt][2] + bx, 0.0f);
        c1[nt][3] = fmaxf(c1[nt][3] + by, 0.0f);
    }

    float c2[8][4];
    #pragma unroll
    for (int nt = 0; nt < 8; nt++)
        #pragma unroll
        for (int e = 0; e < 4; e++) c2[nt][e] = 0.0f;

    #pragma unroll
    for (int ks = 0; ks < 8; ks++) {
        u32 ah0 = cvt_h2(c1[ks][1], c1[ks][0]);
        u32 ah1 = cvt_h2(c1[ks][3], c1[ks][2]);
        const u32* bh = &sw11h[(ks * 4 + kc) * WPAD + gr];
        const u32* bl = &sw11l[(ks * 4 + kc) * WPAD + gr];
        #pragma unroll
        for (int nt = 0; nt < 8; nt++) {
            mma16f(c2[nt], ah0, ah1, ah0, ah1, bh[nt * 8], bl[nt * 8]);
        }
    }

    #pragma unroll
    for (int nt = 0; nt < 8; nt++) {
        float bx = b11[nt * 8 + kc * 2], by = b11[nt * 8 + kc * 2 + 1];
        float* dst = out + r0 * 64 + nt * 8 + kc * 2;
        *(float2*)dst            = make_float2(c2[nt][0] + bx, c2[nt][1] + by);
        *(float2*)(dst + 8 * 64) = make_float2(c2[nt][2] + bx, c2[nt][3] + by);
    }
}

// ---------------------------------------------------------------------------
extern "C" void kernel_launch(void* const* d_in, const int* in_sizes, int n_in,
                              void* d_out, int out_size)
{
    const float* X   = (const float*)d_in[0];
    const float* STE = (const float*)d_in[1];
    const float* W7  = (const float*)d_in[2];
    const float* b7  = (const float*)d_in[3];
    const float* W8  = (const float*)d_in[4];
    const float* b8  = (const float*)d_in[5];
    const float* W9  = (const float*)d_in[6];
    const float* b9  = (const float*)d_in[7];
    const float* W10 = (const float*)d_in[8];
    const float* b10 = (const float*)d_in[9];
    const float* W11 = (const float*)d_in[10];
    const float* b11 = (const float*)d_in[11];
    float* out = (float*)d_out;

    qkv_kernel<<<dim3(TOKENS / 128, 3), 256>>>(X, STE, W7, b7, W8, b8, W9, b9);
    attn_kernel<<<dim3(NBT, KH), 512>>>();
    proj_kernel<<<TOKENS / 128, 256>>>(W10, b10, W11, b11, out);
}

// round 16
// speedup vs baseline: 1.8514x; 1.0642x over previous
#include <cuda_runtime.h>

// Problem constants
#define NBT   96      // B*T
#define NSEQ  512     // N
#define DMODEL 64
#define KH    8
#define HD    8
#define TOKENS (NBT * NSEQ)   // 49152

typedef unsigned long long u64;
typedef unsigned int u32;

// Scratch: q,k,v row-major [h][bt][n][d]; att [tok][64]
__device__ float g_q[KH * NBT * NSEQ * HD];
__device__ float g_k[KH * NBT * NSEQ * HD];
__device__ float g_v[KH * NBT * NSEQ * HD];
__device__ float g_att[TOKENS * DMODEL];

// ---------------- f16 helpers ----------------
// pack {lo16 = f16(x0), hi16 = f16(x1)}
__device__ __forceinline__ u32 cvt_h2(float x1, float x0) {
    u32 r; asm("cvt.rn.f16x2.f32 %0, %1, %2;" : "=r"(r) : "f"(x1), "f"(x0)); return r;
}
__device__ __forceinline__ void h2_to_f32(u32 p, float& lo, float& hi) {
    asm("{\n\t.reg .f16 l, h;\n\tmov.b32 {l, h}, %2;\n\t"
        "cvt.f32.f16 %0, l;\n\tcvt.f32.f16 %1, h;\n\t}"
        : "=f"(lo), "=f"(hi) : "r"(p));
}
__device__ __forceinline__ void split2h(float x0, float x1, u32& hp, u32& lp) {
    hp = cvt_h2(x1, x0);
    float e0, e1; h2_to_f32(hp, e0, e1);
    lp = cvt_h2(x1 - e1, x0 - e0);
}
__device__ __forceinline__ u32 ex2h2(u32 x) {
    u32 y; asm("ex2.approx.f16x2 %0, %1;" : "=r"(y) : "r"(x)); return y;
}
__device__ __forceinline__ u32 hadd2(u32 a, u32 b) {
    u32 d; asm("add.rn.f16x2 %0, %1, %2;" : "=r"(d) : "r"(a), "r"(b)); return d;
}

// ---------------- f16 MMA wrappers ----------------
__device__ __forceinline__ void mma8f(float (&d)[4], u32 a0, u32 a1, u32 b) {
    asm("mma.sync.aligned.m16n8k8.row.col.f32.f16.f16.f32 "
        "{%0,%1,%2,%3},{%4,%5},{%6},{%0,%1,%2,%3};"
        : "+f"(d[0]), "+f"(d[1]), "+f"(d[2]), "+f"(d[3])
        : "r"(a0), "r"(a1), "r"(b));
}
__device__ __forceinline__ void mma16f(float (&d)[4], u32 a0, u32 a1, u32 a2, u32 a3,
                                       u32 b0, u32 b1) {
    asm("mma.sync.aligned.m16n8k16.row.col.f32.f16.f16.f32 "
        "{%0,%1,%2,%3},{%4,%5,%6,%7},{%8,%9},{%0,%1,%2,%3};"
        : "+f"(d[0]), "+f"(d[1]), "+f"(d[2]), "+f"(d[3])
        : "r"(a0), "r"(a1), "r"(a2), "r"(a3), "r"(b0), "r"(b1));
}

#define WPAD 72   // row stride for weight smem planes — proven conflict-free

// ---------------------------------------------------------------------------
// Kernel 1: fused QKV projection, f16 2-term (A single f16, W hi/lo planes).
// Block tile 256 rows x 64 cols: each warp owns 32 rows (2 m-tiles), so every
// B-fragment LDS feeds TWO MMAs — halves smem B-read bytes per FLOP (the
// measured binder at 66% L1). grid (192, 3), 256 threads.
// Outputs row-major [h][bt][n][d].
// ---------------------------------------------------------------------------
__global__ __launch_bounds__(256) void qkv_kernel(
    const float* __restrict__ X, const float* __restrict__ STE,
    const float* __restrict__ W7, const float* __restrict__ b7,
    const float* __restrict__ W8, const float* __restrict__ b8,
    const float* __restrict__ W9, const float* __restrict__ b9)
{
    __shared__ __align__(16) u32 swh[64 * WPAD];
    __shared__ __align__(16) u32 swl[64 * WPAD];

    const int mat = blockIdx.y;
    const float* W  = (mat == 0) ? W7 : (mat == 1) ? W8 : W9;
    const float* bv = (mat == 0) ? b7 : (mat == 1) ? b8 : b9;
    float* gout     = (mat == 0) ? g_q : (mat == 1) ? g_k : g_v;

    const int tid  = threadIdx.x;
    const int lane = tid & 31;
    const int warp = tid >> 5;
    const int row0 = blockIdx.x * 256;
    const int bt   = row0 >> 9;
    const int n0b  = row0 & 511;
    const int gr   = lane >> 2;
    const int kc   = lane & 3;

    #pragma unroll
    for (int e = 0; e < 16; e++) {
        int idx = e * 256 + tid;
        int k2 = idx >> 6, n = idx & 63;
        float w0 = W[(2 * k2) * 64 + n];
        float w1 = W[(2 * k2 + 1) * 64 + n];
        u32 hp, lp;
        split2h(w0, w1, hp, lp);
        swh[k2 * WPAD + n] = hp;
        swl[k2 * WPAD + n] = lp;
    }
    __syncthreads();

    float c[2][8][4];
    #pragma unroll
    for (int mt = 0; mt < 2; mt++)
        #pragma unroll
        for (int nt = 0; nt < 8; nt++)
            #pragma unroll
            for (int e = 0; e < 4; e++) c[mt][nt][e] = 0.0f;

    const int rA = row0 + warp * 32 + gr;        // mt=0 rows: rA, rA+8
    const int rB = rA + 16;                      // mt=1 rows: rB, rB+8

    #pragma unroll 1
    for (int ks = 0; ks < 16; ks++) {
        const float* src = (ks < 8) ? X : STE;
        const int kk = (ks & 7) * 8 + kc * 2;
        float2 fa0 = *(const float2*)(src + rA * 64 + kk);
        float2 fa1 = *(const float2*)(src + (rA + 8) * 64 + kk);
        float2 fb0 = *(const float2*)(src + rB * 64 + kk);
        float2 fb1 = *(const float2*)(src + (rB + 8) * 64 + kk);
        u32 aA0 = cvt_h2(fa0.y, fa0.x);
        u32 aA1 = cvt_h2(fa1.y, fa1.x);
        u32 aB0 = cvt_h2(fb0.y, fb0.x);
        u32 aB1 = cvt_h2(fb1.y, fb1.x);

        const u32* bh = &swh[(ks * 4 + kc) * WPAD + gr];
        const u32* bl = &swl[(ks * 4 + kc) * WPAD + gr];
        #pragma unroll
        for (int nt = 0; nt < 8; nt++) {
            u32 wbh = bh[nt * 8];
            u32 wbl = bl[nt * 8];
            // a·wh (k0..7) + a·wl (k8..15)  ==  a·w, for both m-tiles
            mma16f(c[0][nt], aA0, aA1, aA0, aA1, wbh, wbl);
            mma16f(c[1][nt], aB0, aB1, aB0, aB1, wbh, wbl);
        }
    }

    #pragma unroll
    for (int mt = 0; mt < 2; mt++) {
        const int n_lo = n0b + warp * 32 + mt * 16 + gr;
        #pragma unroll
        for (int nt = 0; nt < 8; nt++) {
            const int d0 = kc * 2;
            float bx = bv[nt * 8 + d0], by = bv[nt * 8 + d0 + 1];
            float2 oA = make_float2(fmaxf(c[mt][nt][0] + bx, 0.0f),
                                    fmaxf(c[mt][nt][1] + by, 0.0f));
            float2 oB = make_float2(fmaxf(c[mt][nt][2] + bx, 0.0f),
                                    fmaxf(c[mt][nt][3] + by, 0.0f));
            float* dst = &gout[(((nt * NBT) + bt) * NSEQ + n_lo) * HD + d0];
            *(float2*)dst            = oA;
            *(float2*)(dst + 8 * HD) = oB;
        }
    }
}

// ---------------------------------------------------------------------------
// Kernel 2: attention per (bt, head), all-f16 (R15 proven version).
// grid (96, 8), 512 threads (16 warps x 32 rows).
// ---------------------------------------------------------------------------
__global__ __launch_bounds__(512) void attn_kernel()
{
    __shared__ __align__(16) u32 skh[NSEQ * 4];       // K f16 pairs [j][c]
    __shared__ __align__(16) u32 svh[(NSEQ / 2) * 8]; // V f16 pairs [j2][d]

    const int bt   = blockIdx.x;
    const int h    = blockIdx.y;
    const int tid  = threadIdx.x;
    const int lane = tid & 31;
    const int warp = tid >> 5;
    const int base = (h * NBT + bt) * NSEQ * HD;

    // stage K -> single f16 pairs over d (one row per thread)
    {
        int r = tid;
        const float4* kp = (const float4*)(g_k + base + r * 8);
        float4 f0 = kp[0], f1 = kp[1];
        *(uint4*)&skh[r * 4] = make_uint4(
            cvt_h2(f0.y, f0.x), cvt_h2(f0.w, f0.z),
            cvt_h2(f1.y, f1.x), cvt_h2(f1.w, f1.z));
    }

    // stage V -> f16 pairs over j at fixed d (one (j2, d-group) per thread)
    {
        int j2 = tid & 255, dg = tid >> 8;
        const float* vb = g_v + base + (2 * j2) * 8 + dg * 4;
        float4 f0 = *(const float4*)vb;        // row 2*j2
        float4 f1 = *(const float4*)(vb + 8);  // row 2*j2+1
        svh[j2 * 8 + dg * 4 + 0] = cvt_h2(f1.x, f0.x);
        svh[j2 * 8 + dg * 4 + 1] = cvt_h2(f1.y, f0.y);
        svh[j2 * 8 + dg * 4 + 2] = cvt_h2(f1.z, f0.z);
        svh[j2 * 8 + dg * 4 + 3] = cvt_h2(f1.w, f0.w);
    }

    // Q A-fragments, log2-domain pre-scale, single f16 (2 m-tiles/warp)
    const float qscale = 0.35355339059327373f * 1.4426950408889634f;
    u32 qh[2][2];
    const int m0 = warp * 32;
    {
        const float* qb = g_q + base;
        #pragma unroll
        for (int mt = 0; mt < 2; mt++) {
            int r = m0 + mt * 16 + (lane >> 2);
            float2 f0 = *(const float2*)(qb + r * 8 + (lane & 3) * 2);
            float2 f1 = *(const float2*)(qb + (r + 8) * 8 + (lane & 3) * 2);
            qh[mt][0] = cvt_h2(f0.y * qscale, f0.x * qscale);
            qh[mt][1] = cvt_h2(f1.y * qscale, f1.x * qscale);
        }
    }
    __syncthreads();

    float o[2][4];
    float l0[2], l1[2];
    #pragma unroll
    for (int mt = 0; mt < 2; mt++) {
        o[mt][0] = o[mt][1] = o[mt][2] = o[mt][3] = 0.0f;
        l0[mt] = 0.0f; l1[mt] = 0.0f;
    }

    const int vb_idx = (lane & 3) * 8 + (lane >> 2);

    #pragma unroll 1
    for (int j0 = 0; j0 < NSEQ; j0 += 16) {
        u32 bkh0 = skh[j0 * 4 + lane];
        u32 bkh1 = skh[(j0 + 8) * 4 + lane];
        u32 bvh0 = svh[(j0 >> 1) * 8 + vb_idx];
        u32 bvh1 = svh[(j0 >> 1) * 8 + 32 + vb_idx];

        #pragma unroll
        for (int mt = 0; mt < 2; mt++) {
            // scores: single-f16 q,k — one mma8 per 8-j chunk
            float s0[4] = {0, 0, 0, 0}, s1[4] = {0, 0, 0, 0};
            mma8f(s0, qh[mt][0], qh[mt][1], bkh0);
            mma8f(s1, qh[mt][0], qh[mt][1], bkh1);

            // pack scores to f16x2 and exp (MUFU; 2 exps/op); result is
            // directly the f16 A-fragment for the PV MMA.
            u32 pa0 = ex2h2(cvt_h2(s0[1], s0[0]));
            u32 pb0 = ex2h2(cvt_h2(s0[3], s0[2]));
            u32 pa1 = ex2h2(cvt_h2(s1[1], s1[0]));
            u32 pb1 = ex2h2(cvt_h2(s1[3], s1[2]));

            // consistent denominator from the same f16 p-hat values
            u32 t0 = hadd2(pa0, pa1);
            u32 t1 = hadd2(pb0, pb1);
            float e0, e1;
            h2_to_f32(t0, e0, e1); l0[mt] += e0 + e1;
            h2_to_f32(t1, e0, e1); l1[mt] += e0 + e1;

            // PV: single f16 mma16 over 16 j's
            mma16f(o[mt], pa0, pb0, pa1, pb1, bvh0, bvh1);
        }
    }

    // normalize and write
    #pragma unroll
    for (int mt = 0; mt < 2; mt++) {
        float a = l0[mt], b = l1[mt];
        a += __shfl_xor_sync(0xffffffffu, a, 1);
        a += __shfl_xor_sync(0xffffffffu, a, 2);
        b += __shfl_xor_sync(0xffffffffu, b, 1);
        b += __shfl_xor_sync(0xffffffffu, b, 2);
        float r0 = __fdividef(1.0f, a);
        float r1 = __fdividef(1.0f, b);

        int row = bt * NSEQ + m0 + mt * 16 + (lane >> 2);
        int col = h * HD + (lane & 3) * 2;
        *(float2*)&g_att[row * DMODEL + col]       = make_float2(o[mt][0] * r0, o[mt][1] * r0);
        *(float2*)&g_att[(row + 8) * DMODEL + col] = make_float2(o[mt][2] * r1, o[mt][3] * r1);
    }
}

// ---------------------------------------------------------------------------
// Kernel 3: out = relu(att @ W10 + b10) @ W11 + b11; f16 2-term on both GEMMs
// (R15 proven version). grid 384, 256 threads.
// ---------------------------------------------------------------------------
__global__ __launch_bounds__(256) void proj_kernel(
    const float* __restrict__ W10, const float* __restrict__ b10,
    const float* __restrict__ W11, const float* __restrict__ b11,
    float* __restrict__ out)
{
    __shared__ __align__(16) u32 sw10h[32 * WPAD];
    __shared__ __align__(16) u32 sw10l[32 * WPAD];
    __shared__ __align__(16) u32 sw11h[32 * WPAD];
    __shared__ __align__(16) u32 sw11l[32 * WPAD];

    const int tid  = threadIdx.x;
    const int lane = tid & 31;
    const int warp = tid >> 5;
    const int gr   = lane >> 2;
    const int kc   = lane & 3;

    #pragma unroll
    for (int e = 0; e < 8; e++) {
        int idx = e * 256 + tid;
        int k2 = idx >> 6, n = idx & 63;
        u32 hp, lp;
        split2h(W10[(2 * k2) * 64 + n], W10[(2 * k2 + 1) * 64 + n], hp, lp);
        sw10h[k2 * WPAD + n] = hp;
        sw10l[k2 * WPAD + n] = lp;
        split2h(W11[(2 * k2) * 64 + n], W11[(2 * k2 + 1) * 64 + n], hp, lp);
        sw11h[k2 * WPAD + n] = hp;
        sw11l[k2 * WPAD + n] = lp;
    }
    __syncthreads();

    const int r0 = blockIdx.x * 128 + warp * 16 + gr;

    float c1[8][4];
    #pragma unroll
    for (int nt = 0; nt < 8; nt++)
        #pragma unroll
        for (int e = 0; e < 4; e++) c1[nt][e] = 0.0f;

    #pragma unroll
    for (int ks = 0; ks < 8; ks++) {
        const int kk = ks * 8 + kc * 2;
        float2 f0 = *(const float2*)(g_att + r0 * 64 + kk);
        float2 f1 = *(const float2*)(g_att + (r0 + 8) * 64 + kk);
        u32 ah0 = cvt_h2(f0.y, f0.x);
        u32 ah1 = cvt_h2(f1.y, f1.x);
        const u32* bh = &sw10h[(ks * 4 + kc) * WPAD + gr];
        const u32* bl = &sw10l[(ks * 4 + kc) * WPAD + gr];
        #pragma unroll
        for (int nt = 0; nt < 8; nt++) {
            mma16f(c1[nt], ah0, ah1, ah0, ah1, bh[nt * 8], bl[nt * 8]);
        }
    }

    #pragma unroll
    for (int nt = 0; nt < 8; nt++) {
        float bx = b10[nt * 8 + kc * 2], by = b10[nt * 8 + kc * 2 + 1];
        c1[nt][0] = fmaxf(c1[nt][0] + bx, 0.0f);
        c1[nt][1] = fmaxf(c1[nt][1] + by, 0.0f);
        c1[nt][2] = fmaxf(c1[nt][2] + bx, 0.0f);
        c1[nt][3] = fmaxf(c1[nt][3] + by, 0.0f);
    }

    float c2[8][4];
    #pragma unroll
    for (int nt = 0; nt < 8; nt++)
        #pragma unroll
        for (int e = 0; e < 4; e++) c2[nt][e] = 0.0f;

    #pragma unroll
    for (int ks = 0; ks < 8; ks++) {
        u32 ah0 = cvt_h2(c1[ks][1], c1[ks][0]);
        u32 ah1 = cvt_h2(c1[ks][3], c1[ks][2]);
        const u32* bh = &sw11h[(ks * 4 + kc) * WPAD + gr];
        const u32* bl = &sw11l[(ks * 4 + kc) * WPAD + gr];
        #pragma unroll
        for (int nt = 0; nt < 8; nt++) {
            mma16f(c2[nt], ah0, ah1, ah0, ah1, bh[nt * 8], bl[nt * 8]);
        }
    }

    #pragma unroll
    for (int nt = 0; nt < 8; nt++) {
        float bx = b11[nt * 8 + kc * 2], by = b11[nt * 8 + kc * 2 + 1];
        float* dst = out + r0 * 64 + nt * 8 + kc * 2;
        *(float2*)dst            = make_float2(c2[nt][0] + bx, c2[nt][1] + by);
        *(float2*)(dst + 8 * 64) = make_float2(c2[nt][2] + bx, c2[nt][3] + by);
    }
}

// ---------------------------------------------------------------------------
extern "C" void kernel_launch(void* const* d_in, const int* in_sizes, int n_in,
                              void* d_out, int out_size)
{
    const float* X   = (const float*)d_in[0];
    const float* STE = (const float*)d_in[1];
    const float* W7  = (const float*)d_in[2];
    const float* b7  = (const float*)d_in[3];
    const float* W8  = (const float*)d_in[4];
    const float* b8  = (const float*)d_in[5];
    const float* W9  = (const float*)d_in[6];
    const float* b9  = (const float*)d_in[7];
    const float* W10 = (const float*)d_in[8];
    const float* b10 = (const float*)d_in[9];
    const float* W11 = (const float*)d_in[10];
    const float* b11 = (const float*)d_in[11];
    float* out = (float*)d_out;

    qkv_kernel<<<dim3(TOKENS / 256, 3), 256>>>(X, STE, W7, b7, W8, b8, W9, b9);
    attn_kernel<<<dim3(NBT, KH), 512>>>();
    proj_kernel<<<TOKENS / 128, 256>>>(W10, b10, W11, b11, out);
}

// round 17
// speedup vs baseline: 1.8785x; 1.0146x over previous
#include <cuda_runtime.h>

// Problem constants
#define NBT   96      // B*T
#define NSEQ  512     // N
#define DMODEL 64
#define KH    8
#define HD    8
#define TOKENS (NBT * NSEQ)   // 49152

typedef unsigned long long u64;
typedef unsigned int u32;

// Scratch: q,k,v row-major [h][bt][n][d]; att [tok][64]
__device__ float g_q[KH * NBT * NSEQ * HD];
__device__ float g_k[KH * NBT * NSEQ * HD];
__device__ float g_v[KH * NBT * NSEQ * HD];
__device__ float g_att[TOKENS * DMODEL];

// ---------------- f16 helpers ----------------
// pack {lo16 = f16(x0), hi16 = f16(x1)}
__device__ __forceinline__ u32 cvt_h2(float x1, float x0) {
    u32 r; asm("cvt.rn.f16x2.f32 %0, %1, %2;" : "=r"(r) : "f"(x1), "f"(x0)); return r;
}
__device__ __forceinline__ void h2_to_f32(u32 p, float& lo, float& hi) {
    asm("{\n\t.reg .f16 l, h;\n\tmov.b32 {l, h}, %2;\n\t"
        "cvt.f32.f16 %0, l;\n\tcvt.f32.f16 %1, h;\n\t}"
        : "=f"(lo), "=f"(hi) : "r"(p));
}
__device__ __forceinline__ void split2h(float x0, float x1, u32& hp, u32& lp) {
    hp = cvt_h2(x1, x0);
    float e0, e1; h2_to_f32(hp, e0, e1);
    lp = cvt_h2(x1 - e1, x0 - e0);
}
__device__ __forceinline__ u32 ex2h2(u32 x) {
    u32 y; asm("ex2.approx.f16x2 %0, %1;" : "=r"(y) : "r"(x)); return y;
}
__device__ __forceinline__ u32 hadd2(u32 a, u32 b) {
    u32 d; asm("add.rn.f16x2 %0, %1, %2;" : "=r"(d) : "r"(a), "r"(b)); return d;
}

// ---------------- f16 MMA wrappers ----------------
__device__ __forceinline__ void mma8f(float (&d)[4], u32 a0, u32 a1, u32 b) {
    asm("mma.sync.aligned.m16n8k8.row.col.f32.f16.f16.f32 "
        "{%0,%1,%2,%3},{%4,%5},{%6},{%0,%1,%2,%3};"
        : "+f"(d[0]), "+f"(d[1]), "+f"(d[2]), "+f"(d[3])
        : "r"(a0), "r"(a1), "r"(b));
}
// f16-accumulator variant: D comes out as packed f16x2 pairs {c0,c1},{c2,c3}
__device__ __forceinline__ void mma8h(u32 (&d)[2], u32 a0, u32 a1, u32 b) {
    asm("mma.sync.aligned.m16n8k8.row.col.f16.f16.f16.f16 "
        "{%0,%1},{%2,%3},{%4},{%0,%1};"
        : "+r"(d[0]), "+r"(d[1])
        : "r"(a0), "r"(a1), "r"(b));
}
__device__ __forceinline__ void mma16f(float (&d)[4], u32 a0, u32 a1, u32 a2, u32 a3,
                                       u32 b0, u32 b1) {
    asm("mma.sync.aligned.m16n8k16.row.col.f32.f16.f16.f32 "
        "{%0,%1,%2,%3},{%4,%5,%6,%7},{%8,%9},{%0,%1,%2,%3};"
        : "+f"(d[0]), "+f"(d[1]), "+f"(d[2]), "+f"(d[3])
        : "r"(a0), "r"(a1), "r"(a2), "r"(a3), "r"(b0), "r"(b1));
}

#define WPAD 72   // row stride for weight smem planes — proven conflict-free

// ---------------------------------------------------------------------------
// Kernel 1: fused QKV projection, f16 2-term. Block owns 512 rows (one bt):
// W staged/split ONCE, then two sequential 256-row tile passes (each warp
// 32 rows = 2 m-tiles, so every B-fragment LDS feeds two MMAs).
// grid (96, 3), 256 threads. Outputs row-major [h][bt][n][d].
// ---------------------------------------------------------------------------
__global__ __launch_bounds__(256) void qkv_kernel(
    const float* __restrict__ X, const float* __restrict__ STE,
    const float* __restrict__ W7, const float* __restrict__ b7,
    const float* __restrict__ W8, const float* __restrict__ b8,
    const float* __restrict__ W9, const float* __restrict__ b9)
{
    __shared__ __align__(16) u32 swh[64 * WPAD];
    __shared__ __align__(16) u32 swl[64 * WPAD];

    const int mat = blockIdx.y;
    const float* W  = (mat == 0) ? W7 : (mat == 1) ? W8 : W9;
    const float* bv = (mat == 0) ? b7 : (mat == 1) ? b8 : b9;
    float* gout     = (mat == 0) ? g_q : (mat == 1) ? g_k : g_v;

    const int tid  = threadIdx.x;
    const int lane = tid & 31;
    const int warp = tid >> 5;
    const int bt   = blockIdx.x;          // block = one full bt (512 rows)
    const int gr   = lane >> 2;
    const int kc   = lane & 3;

    #pragma unroll
    for (int e = 0; e < 16; e++) {
        int idx = e * 256 + tid;
        int k2 = idx >> 6, n = idx & 63;
        float w0 = W[(2 * k2) * 64 + n];
        float w1 = W[(2 * k2 + 1) * 64 + n];
        u32 hp, lp;
        split2h(w0, w1, hp, lp);
        swh[k2 * WPAD + n] = hp;
        swl[k2 * WPAD + n] = lp;
    }
    __syncthreads();

    #pragma unroll 1
    for (int t = 0; t < 2; t++) {
        const int row0 = bt * 512 + t * 256;
        const int n0b  = t * 256;

        float c[2][8][4];
        #pragma unroll
        for (int mt = 0; mt < 2; mt++)
            #pragma unroll
            for (int nt = 0; nt < 8; nt++)
                #pragma unroll
                for (int e = 0; e < 4; e++) c[mt][nt][e] = 0.0f;

        const int rA = row0 + warp * 32 + gr;
        const int rB = rA + 16;

        #pragma unroll 1
        for (int ks = 0; ks < 16; ks++) {
            const float* src = (ks < 8) ? X : STE;
            const int kk = (ks & 7) * 8 + kc * 2;
            float2 fa0 = *(const float2*)(src + rA * 64 + kk);
            float2 fa1 = *(const float2*)(src + (rA + 8) * 64 + kk);
            float2 fb0 = *(const float2*)(src + rB * 64 + kk);
            float2 fb1 = *(const float2*)(src + (rB + 8) * 64 + kk);
            u32 aA0 = cvt_h2(fa0.y, fa0.x);
            u32 aA1 = cvt_h2(fa1.y, fa1.x);
            u32 aB0 = cvt_h2(fb0.y, fb0.x);
            u32 aB1 = cvt_h2(fb1.y, fb1.x);

            const u32* bh = &swh[(ks * 4 + kc) * WPAD + gr];
            const u32* bl = &swl[(ks * 4 + kc) * WPAD + gr];
            #pragma unroll
            for (int nt = 0; nt < 8; nt++) {
                u32 wbh = bh[nt * 8];
                u32 wbl = bl[nt * 8];
                mma16f(c[0][nt], aA0, aA1, aA0, aA1, wbh, wbl);
                mma16f(c[1][nt], aB0, aB1, aB0, aB1, wbh, wbl);
            }
        }

        #pragma unroll
        for (int mt = 0; mt < 2; mt++) {
            const int n_lo = n0b + warp * 32 + mt * 16 + gr;
            #pragma unroll
            for (int nt = 0; nt < 8; nt++) {
                const int d0 = kc * 2;
                float bx = bv[nt * 8 + d0], by = bv[nt * 8 + d0 + 1];
                float2 oA = make_float2(fmaxf(c[mt][nt][0] + bx, 0.0f),
                                        fmaxf(c[mt][nt][1] + by, 0.0f));
                float2 oB = make_float2(fmaxf(c[mt][nt][2] + bx, 0.0f),
                                        fmaxf(c[mt][nt][3] + by, 0.0f));
                float* dst = &gout[(((nt * NBT) + bt) * NSEQ + n_lo) * HD + d0];
                *(float2*)dst            = oA;
                *(float2*)(dst + 8 * HD) = oB;
            }
        }
    }
}

// ---------------------------------------------------------------------------
// Kernel 2: attention per (bt, head), all-f16, with f16-ACCUMULATOR score
// MMAs: the packed f16x2 D-fragment feeds ex2h2 directly (no cvt repack) and
// the exp output is directly the PV A-fragment. Consistent denominator.
// grid (96, 8), 512 threads (16 warps x 32 rows).
// ---------------------------------------------------------------------------
__global__ __launch_bounds__(512) void attn_kernel()
{
    __shared__ __align__(16) u32 skh[NSEQ * 4];       // K f16 pairs [j][c]
    __shared__ __align__(16) u32 svh[(NSEQ / 2) * 8]; // V f16 pairs [j2][d]

    const int bt   = blockIdx.x;
    const int h    = blockIdx.y;
    const int tid  = threadIdx.x;
    const int lane = tid & 31;
    const int warp = tid >> 5;
    const int base = (h * NBT + bt) * NSEQ * HD;

    // stage K -> single f16 pairs over d (one row per thread)
    {
        int r = tid;
        const float4* kp = (const float4*)(g_k + base + r * 8);
        float4 f0 = kp[0], f1 = kp[1];
        *(uint4*)&skh[r * 4] = make_uint4(
            cvt_h2(f0.y, f0.x), cvt_h2(f0.w, f0.z),
            cvt_h2(f1.y, f1.x), cvt_h2(f1.w, f1.z));
    }

    // stage V -> f16 pairs over j at fixed d (one (j2, d-group) per thread)
    {
        int j2 = tid & 255, dg = tid >> 8;
        const float* vb = g_v + base + (2 * j2) * 8 + dg * 4;
        float4 f0 = *(const float4*)vb;        // row 2*j2
        float4 f1 = *(const float4*)(vb + 8);  // row 2*j2+1
        svh[j2 * 8 + dg * 4 + 0] = cvt_h2(f1.x, f0.x);
        svh[j2 * 8 + dg * 4 + 1] = cvt_h2(f1.y, f0.y);
        svh[j2 * 8 + dg * 4 + 2] = cvt_h2(f1.z, f0.z);
        svh[j2 * 8 + dg * 4 + 3] = cvt_h2(f1.w, f0.w);
    }

    // Q A-fragments, log2-domain pre-scale, single f16 (2 m-tiles/warp)
    const float qscale = 0.35355339059327373f * 1.4426950408889634f;
    u32 qh[2][2];
    const int m0 = warp * 32;
    {
        const float* qb = g_q + base;
        #pragma unroll
        for (int mt = 0; mt < 2; mt++) {
            int r = m0 + mt * 16 + (lane >> 2);
            float2 f0 = *(const float2*)(qb + r * 8 + (lane & 3) * 2);
            float2 f1 = *(const float2*)(qb + (r + 8) * 8 + (lane & 3) * 2);
            qh[mt][0] = cvt_h2(f0.y * qscale, f0.x * qscale);
            qh[mt][1] = cvt_h2(f1.y * qscale, f1.x * qscale);
        }
    }
    __syncthreads();

    float o[2][4];
    float l0[2], l1[2];
    #pragma unroll
    for (int mt = 0; mt < 2; mt++) {
        o[mt][0] = o[mt][1] = o[mt][2] = o[mt][3] = 0.0f;
        l0[mt] = 0.0f; l1[mt] = 0.0f;
    }

    const int vb_idx = (lane & 3) * 8 + (lane >> 2);

    #pragma unroll 1
    for (int j0 = 0; j0 < NSEQ; j0 += 16) {
        u32 bkh0 = skh[j0 * 4 + lane];
        u32 bkh1 = skh[(j0 + 8) * 4 + lane];
        u32 bvh0 = svh[(j0 >> 1) * 8 + vb_idx];
        u32 bvh1 = svh[(j0 >> 1) * 8 + 32 + vb_idx];

        #pragma unroll
        for (int mt = 0; mt < 2; mt++) {
            // scores with f16 accumulators: D regs are packed {c0,c1},{c2,c3}
            u32 sd0[2] = {0u, 0u}, sd1[2] = {0u, 0u};
            mma8h(sd0, qh[mt][0], qh[mt][1], bkh0);
            mma8h(sd1, qh[mt][0], qh[mt][1], bkh1);

            // exp (MUFU, 2 exps/op) straight off the MMA destination regs;
            // result is directly the f16 A-fragment for the PV MMA.
            u32 pa0 = ex2h2(sd0[0]);
            u32 pb0 = ex2h2(sd0[1]);
            u32 pa1 = ex2h2(sd1[0]);
            u32 pb1 = ex2h2(sd1[1]);

            // consistent denominator from the same f16 p-hat values
            u32 t0 = hadd2(pa0, pa1);
            u32 t1 = hadd2(pb0, pb1);
            float e0, e1;
            h2_to_f32(t0, e0, e1); l0[mt] += e0 + e1;
            h2_to_f32(t1, e0, e1); l1[mt] += e0 + e1;

            // PV: single f16 mma16 over 16 j's
            mma16f(o[mt], pa0, pb0, pa1, pb1, bvh0, bvh1);
        }
    }

    // normalize and write
    #pragma unroll
    for (int mt = 0; mt < 2; mt++) {
        float a = l0[mt], b = l1[mt];
        a += __shfl_xor_sync(0xffffffffu, a, 1);
        a += __shfl_xor_sync(0xffffffffu, a, 2);
        b += __shfl_xor_sync(0xffffffffu, b, 1);
        b += __shfl_xor_sync(0xffffffffu, b, 2);
        float r0 = __fdividef(1.0f, a);
        float r1 = __fdividef(1.0f, b);

        int row = bt * NSEQ + m0 + mt * 16 + (lane >> 2);
        int col = h * HD + (lane & 3) * 2;
        *(float2*)&g_att[row * DMODEL + col]       = make_float2(o[mt][0] * r0, o[mt][1] * r0);
        *(float2*)&g_att[(row + 8) * DMODEL + col] = make_float2(o[mt][2] * r1, o[mt][3] * r1);
    }
}

// ---------------------------------------------------------------------------
// Kernel 3: out = relu(att @ W10 + b10) @ W11 + b11; f16 2-term on both GEMMs
// (R15 proven version). grid 384, 256 threads.
// ---------------------------------------------------------------------------
__global__ __launch_bounds__(256) void proj_kernel(
    const float* __restrict__ W10, const float* __restrict__ b10,
    const float* __restrict__ W11, const float* __restrict__ b11,
    float* __restrict__ out)
{
    __shared__ __align__(16) u32 sw10h[32 * WPAD];
    __shared__ __align__(16) u32 sw10l[32 * WPAD];
    __shared__ __align__(16) u32 sw11h[32 * WPAD];
    __shared__ __align__(16) u32 sw11l[32 * WPAD];

    const int tid  = threadIdx.x;
    const int lane = tid & 31;
    const int warp = tid >> 5;
    const int gr   = lane >> 2;
    const int kc   = lane & 3;

    #pragma unroll
    for (int e = 0; e < 8; e++) {
        int idx = e * 256 + tid;
        int k2 = idx >> 6, n = idx & 63;
        u32 hp, lp;
        split2h(W10[(2 * k2) * 64 + n], W10[(2 * k2 + 1) * 64 + n], hp, lp);
        sw10h[k2 * WPAD + n] = hp;
        sw10l[k2 * WPAD + n] = lp;
        split2h(W11[(2 * k2) * 64 + n], W11[(2 * k2 + 1) * 64 + n], hp, lp);
        sw11h[k2 * WPAD + n] = hp;
        sw11l[k2 * WPAD + n] = lp;
    }
    __syncthreads();

    const int r0 = blockIdx.x * 128 + warp * 16 + gr;

    float c1[8][4];
    #pragma unroll
    for (int nt = 0; nt < 8; nt++)
        #pragma unroll
        for (int e = 0; e < 4; e++) c1[nt][e] = 0.0f;

    #pragma unroll
    for (int ks = 0; ks < 8; ks++) {
        const int kk = ks * 8 + kc * 2;
        float2 f0 = *(const float2*)(g_att + r0 * 64 + kk);
        float2 f1 = *(const float2*)(g_att + (r0 + 8) * 64 + kk);
        u32 ah0 = cvt_h2(f0.y, f0.x);
        u32 ah1 = cvt_h2(f1.y, f1.x);
        const u32* bh = &sw10h[(ks * 4 + kc) * WPAD + gr];
        const u32* bl = &sw10l[(ks * 4 + kc) * WPAD + gr];
        #pragma unroll
        for (int nt = 0; nt < 8; nt++) {
            mma16f(c1[nt], ah0, ah1, ah0, ah1, bh[nt * 8], bl[nt * 8]);
        }
    }

    #pragma unroll
    for (int nt = 0; nt < 8; nt++) {
        float bx = b10[nt * 8 + kc * 2], by = b10[nt * 8 + kc * 2 + 1];
        c1[nt][0] = fmaxf(c1[nt][0] + bx, 0.0f);
        c1[nt][1] = fmaxf(c1[nt][1] + by, 0.0f);
        c1[nt][2] = fmaxf(c1[nt][2] + bx, 0.0f);
        c1[nt][3] = fmaxf(c1[nt][3] + by, 0.0f);
    }

    float c2[8][4];
    #pragma unroll
    for (int nt = 0; nt < 8; nt++)
        #pragma unroll
        for (int e = 0; e < 4; e++) c2[nt][e] = 0.0f;

    #pragma unroll
    for (int ks = 0; ks < 8; ks++) {
        u32 ah0 = cvt_h2(c1[ks][1], c1[ks][0]);
        u32 ah1 = cvt_h2(c1[ks][3], c1[ks][2]);
        const u32* bh = &sw11h[(ks * 4 + kc) * WPAD + gr];
        const u32* bl = &sw11l[(ks * 4 + kc) * WPAD + gr];
        #pragma unroll
        for (int nt = 0; nt < 8; nt++) {
            mma16f(c2[nt], ah0, ah1, ah0, ah1, bh[nt * 8], bl[nt * 8]);
        }
    }

    #pragma unroll
    for (int nt = 0; nt < 8; nt++) {
        float bx = b11[nt * 8 + kc * 2], by = b11[nt * 8 + kc * 2 + 1];
        float* dst = out + r0 * 64 + nt * 8 + kc * 2;
        *(float2*)dst            = make_float2(c2[nt][0] + bx, c2[nt][1] + by);
        *(float2*)(dst + 8 * 64) = make_float2(c2[nt][2] + bx, c2[nt][3] + by);
    }
}

// ---------------------------------------------------------------------------
extern "C" void kernel_launch(void* const* d_in, const int* in_sizes, int n_in,
                              void* d_out, int out_size)
{
    const float* X   = (const float*)d_in[0];
    const float* STE = (const float*)d_in[1];
    const float* W7  = (const float*)d_in[2];
    const float* b7  = (const float*)d_in[3];
    const float* W8  = (const float*)d_in[4];
    const float* b8  = (const float*)d_in[5];
    const float* W9  = (const float*)d_in[6];
    const float* b9  = (const float*)d_in[7];
    const float* W10 = (const float*)d_in[8];
    const float* b10 = (const float*)d_in[9];
    const float* W11 = (const float*)d_in[10];
    const float* b11 = (const float*)d_in[11];
    float* out = (float*)d_out;

    qkv_kernel<<<dim3(NBT, 3), 256>>>(X, STE, W7, b7, W8, b8, W9, b9);
    attn_kernel<<<dim3(NBT, KH), 512>>>();
    proj_kernel<<<TOKENS / 128, 256>>>(W10, b10, W11, b11, out);
}